// round 10
// baseline (speedup 1.0000x reference)
#include <cuda_runtime.h>
#include <cuda_bf16.h>
#include <cuda_fp16.h>
#include <cstdint>
#include <math.h>

#define BATCH 8
#define LSEQ  2048
#define DDIM  512

// ---------------------------------------------------------------------------
// Device-global scratch (module-load allocation; no runtime allocs).
// ---------------------------------------------------------------------------
static __device__ float g_P[(size_t)BATCH * LSEQ * LSEQ];                           // 128 MiB logits
static __device__ __align__(128) __nv_bfloat16 g_qh[(size_t)BATCH * LSEQ * DDIM];
static __device__ __align__(128) __nv_bfloat16 g_ql[(size_t)BATCH * LSEQ * DDIM];
static __device__ __align__(128) __nv_bfloat16 g_kh[(size_t)BATCH * LSEQ * DDIM];
static __device__ __align__(128) __nv_bfloat16 g_kl[(size_t)BATCH * LSEQ * DDIM];
static __device__ __align__(128) __half g_vtf[(size_t)BATCH * DDIM * LSEQ];         // v^T fp16 [b][d][j]
static __device__ __align__(128) __half g_af[(size_t)BATCH * LSEQ * LSEQ];          // attn fp16

// ---------------------------------------------------------------------------
// PTX helpers (sm_80+ only; base sm_103 target has no tcgen05)
// ---------------------------------------------------------------------------
__device__ __forceinline__ uint32_t smem_u32(const void* p) {
    uint32_t a;
    asm("{ .reg .u64 t; cvta.to.shared.u64 t, %1; cvt.u32.u64 %0, t; }" : "=r"(a) : "l"(p));
    return a;
}
__device__ __forceinline__ void ldsm4(uint32_t* r, uint32_t addr) {
    asm volatile("ldmatrix.sync.aligned.m8n8.x4.shared.b16 {%0,%1,%2,%3}, [%4];"
                 : "=r"(r[0]), "=r"(r[1]), "=r"(r[2]), "=r"(r[3]) : "r"(addr));
}
#define MMA_BF16(d, a, b0, b1)                                                     \
    asm volatile("mma.sync.aligned.m16n8k16.row.col.f32.bf16.bf16.f32 "            \
                 "{%0,%1,%2,%3},{%4,%5,%6,%7},{%8,%9},{%0,%1,%2,%3};"              \
                 : "+f"((d)[0]), "+f"((d)[1]), "+f"((d)[2]), "+f"((d)[3])          \
                 : "r"((a)[0]), "r"((a)[1]), "r"((a)[2]), "r"((a)[3]),             \
                   "r"(b0), "r"(b1))
#define MMA_F16(d, a, b0, b1)                                                      \
    asm volatile("mma.sync.aligned.m16n8k16.row.col.f32.f16.f16.f32 "              \
                 "{%0,%1,%2,%3},{%4,%5,%6,%7},{%8,%9},{%0,%1,%2,%3};"              \
                 : "+f"((d)[0]), "+f"((d)[1]), "+f"((d)[2]), "+f"((d)[3])          \
                 : "r"((a)[0]), "r"((a)[1]), "r"((a)[2]), "r"((a)[3]),             \
                   "r"(b0), "r"(b1))
#define CP_ASYNC16(dst, src) \
    asm volatile("cp.async.cg.shared.global [%0], [%1], 16;" :: "r"(dst), "l"(src))
#define CP_COMMIT()  asm volatile("cp.async.commit_group;" ::: "memory")
#define CP_WAITN(n)  asm volatile("cp.async.wait_group %0;" :: "n"(n) : "memory")

__device__ __forceinline__ void split2(float v, __nv_bfloat16& h, __nv_bfloat16& l) {
    h = __float2bfloat16(v);
    l = __float2bfloat16(v - __bfloat162float(h));
}

// Swizzle for 64-byte rows (4 x 16B segs): seg ^= (row>>1)&3
__device__ __forceinline__ uint32_t swz64(int row, int seg) {
    return (uint32_t)(row * 64 + ((seg ^ ((row >> 1) & 3)) << 4));
}
// Swizzle for 128-byte rows (8 x 16B segs): seg ^= row&7
__device__ __forceinline__ uint32_t swz128(int row, int seg) {
    return (uint32_t)(row * 128 + ((seg ^ (row & 7)) << 4));
}

// ---------------------------------------------------------------------------
// Kernel 1: split projections for ONE batch. q,k -> bf16 hi/lo [b][i][d];
// v -> fp16, transposed [b][d][j]. Block = 64(j) x 64(d). Grid (32, 8).
// ---------------------------------------------------------------------------
__global__ __launch_bounds__(256) void split_kernel(const float* __restrict__ x,
                                                    const float* __restrict__ qw,
                                                    const float* __restrict__ kw,
                                                    const float* __restrict__ vw,
                                                    int b)
{
    __shared__ __half vf_s[64][66];

    const int j0 = blockIdx.x * 64;
    const int d0 = blockIdx.y * 64;
    const int t  = threadIdx.x;

    union U4 { __nv_bfloat16 h[4]; uint2 u; };

#pragma unroll
    for (int it = 0; it < 4; ++it) {
        const int id = t + it * 256;
        const int r  = id >> 4;
        const int c  = (id & 15) * 4;
        const size_t gx = ((size_t)b * LSEQ + j0 + r) * DDIM + d0 + c;
        const size_t gw = (size_t)(j0 + r) * DDIM + d0 + c;
        const float4 xv = *(const float4*)(x  + gx);
        const float4 q4 = *(const float4*)(qw + gw);
        const float4 k4 = *(const float4*)(kw + gw);
        const float4 v4 = *(const float4*)(vw + gw);

        U4 qh, ql, kh, kl;
        split2(xv.x * q4.x, qh.h[0], ql.h[0]); split2(xv.y * q4.y, qh.h[1], ql.h[1]);
        split2(xv.z * q4.z, qh.h[2], ql.h[2]); split2(xv.w * q4.w, qh.h[3], ql.h[3]);
        split2(xv.x * k4.x, kh.h[0], kl.h[0]); split2(xv.y * k4.y, kh.h[1], kl.h[1]);
        split2(xv.z * k4.z, kh.h[2], kl.h[2]); split2(xv.w * k4.w, kh.h[3], kl.h[3]);
        *(uint2*)(g_qh + gx) = qh.u;  *(uint2*)(g_ql + gx) = ql.u;
        *(uint2*)(g_kh + gx) = kh.u;  *(uint2*)(g_kl + gx) = kl.u;

        vf_s[r][c + 0] = __float2half(xv.x * v4.x);
        vf_s[r][c + 1] = __float2half(xv.y * v4.y);
        vf_s[r][c + 2] = __float2half(xv.z * v4.z);
        vf_s[r][c + 3] = __float2half(xv.w * v4.w);
    }
    __syncthreads();

#pragma unroll
    for (int it = 0; it < 2; ++it) {
        const int id = t + it * 256;
        const int dr = id >> 3;
        const int jg = (id & 7) * 8;
        __half tmp[8];
#pragma unroll
        for (int j = 0; j < 8; ++j) tmp[j] = vf_s[jg + j][dr];
        *(uint4*)(g_vtf + ((size_t)b * DDIM + d0 + dr) * LSEQ + j0 + jg) =
            *(const uint4*)tmp;
    }
}

// ---------------------------------------------------------------------------
// Kernel 2: QK 3-product bf16 HMMA GEMM, one batch. Tile 128x128, K-chunk 32,
// 3-stage cp.async, 2 CTAs/SM. Grid (16, 16).
// ---------------------------------------------------------------------------
__global__ __launch_bounds__(256, 2) void qk_kernel(int b)
{
    extern __shared__ __align__(128) char dsm[];

    constexpr int K       = DDIM;
    constexpr int NC      = K / 32;        // 16
    constexpr int TILE_B  = 128 * 64;      // 8 KB
    constexpr int STAGE_B = 4 * TILE_B;    // 32 KB
    const float scale = 0.3535533905932738f;

    const int n0 = blockIdx.x * 128;
    const int m0 = blockIdx.y * 128;
    const int t    = threadIdx.x;
    const int lane = t & 31;
    const int wid  = t >> 5;
    const int wm   = wid & 1;
    const int wn   = wid >> 1;

    const __nv_bfloat16* pAh = g_qh + ((size_t)b * LSEQ + m0) * K;
    const __nv_bfloat16* pAl = g_ql + ((size_t)b * LSEQ + m0) * K;
    const __nv_bfloat16* pBh = g_kh + ((size_t)b * LSEQ + n0) * K;
    const __nv_bfloat16* pBl = g_kl + ((size_t)b * LSEQ + n0) * K;
    float* Cb = g_P + ((size_t)b * LSEQ + m0) * LSEQ + n0;

    const uint32_t sb = smem_u32(dsm);

    auto prefetch = [&](int c, int s) {
        const int k0 = c * 32;
        const uint32_t st = sb + s * STAGE_B;
        const __nv_bfloat16* gs[4] = { pAh + k0, pAl + k0, pBh + k0, pBl + k0 };
#pragma unroll
        for (int tt = 0; tt < 4; ++tt) {
            const uint32_t tb = st + tt * TILE_B;
#pragma unroll
            for (int i = 0; i < 2; ++i) {
                const int li  = t + i * 256;
                const int row = li >> 2;
                const int seg = li & 3;
                CP_ASYNC16(tb + swz64(row, seg), gs[tt] + (size_t)row * K + seg * 8);
            }
        }
        CP_COMMIT();
    };

    float acc[4][4][4];
#pragma unroll
    for (int mf = 0; mf < 4; ++mf)
#pragma unroll
        for (int nf = 0; nf < 4; ++nf)
#pragma unroll
            for (int i = 0; i < 4; ++i) acc[mf][nf][i] = 0.0f;

    const int lr   = lane & 15;
    const int lseg = lane >> 4;

    prefetch(0, 0);
    prefetch(1, 1);

    int s = 0;
    for (int c = 0; c < NC; ++c) {
        if (c + 1 < NC) { CP_WAITN(1); } else { CP_WAITN(0); }
        __syncthreads();

        const uint32_t st  = sb + s * STAGE_B;
        const uint32_t sAh = st;
        const uint32_t sAl = st + TILE_B;
        const uint32_t sBh = st + 2 * TILE_B;
        const uint32_t sBl = st + 3 * TILE_B;

#pragma unroll
        for (int ks = 0; ks < 2; ++ks) {
            const int segk = ks * 2 + lseg;
            uint32_t ah[4][4], al[4][4], bh[2][4], bl[2][4];
#pragma unroll
            for (int mf = 0; mf < 4; ++mf) {
                const uint32_t off = swz64(wm * 64 + mf * 16 + lr, segk);
                ldsm4(ah[mf], sAh + off);
                ldsm4(al[mf], sAl + off);
            }
#pragma unroll
            for (int p = 0; p < 2; ++p) {
                const uint32_t off = swz64(wn * 32 + p * 16 + lr, segk);
                ldsm4(bh[p], sBh + off);
                ldsm4(bl[p], sBl + off);
            }
#pragma unroll
            for (int mf = 0; mf < 4; ++mf)
#pragma unroll
                for (int nf = 0; nf < 4; ++nf) {
                    const int p = nf >> 1, s2 = nf & 1;
                    MMA_BF16(acc[mf][nf], ah[mf], bh[p][s2], bh[p][s2 + 2]);
                }
#pragma unroll
            for (int mf = 0; mf < 4; ++mf)
#pragma unroll
                for (int nf = 0; nf < 4; ++nf) {
                    const int p = nf >> 1, s2 = nf & 1;
                    MMA_BF16(acc[mf][nf], al[mf], bh[p][s2], bh[p][s2 + 2]);
                }
#pragma unroll
            for (int mf = 0; mf < 4; ++mf)
#pragma unroll
                for (int nf = 0; nf < 4; ++nf) {
                    const int p = nf >> 1, s2 = nf & 1;
                    MMA_BF16(acc[mf][nf], ah[mf], bl[p][s2], bl[p][s2 + 2]);
                }
        }

        if (c + 2 < NC) {
            int s2 = s + 2; if (s2 >= 3) s2 -= 3;
            prefetch(c + 2, s2);
        }
        if (++s == 3) s = 0;
    }

#pragma unroll
    for (int mf = 0; mf < 4; ++mf) {
#pragma unroll
        for (int nf = 0; nf < 4; ++nf) {
            const int r0 = wm * 64 + mf * 16 + (lane >> 2);
            const int cc = wn * 32 + nf * 8 + (lane & 3) * 2;
            float2 v0, v1;
            v0.x = acc[mf][nf][0] * scale; v0.y = acc[mf][nf][1] * scale;
            v1.x = acc[mf][nf][2] * scale; v1.y = acc[mf][nf][3] * scale;
            *(float2*)&Cb[(size_t)r0 * LSEQ + cc]       = v0;
            *(float2*)&Cb[(size_t)(r0 + 8) * LSEQ + cc] = v1;
        }
    }
}

// ---------------------------------------------------------------------------
// Kernel 3: row softmax over g_P for one batch -> fp16 attention g_af.
// Shuffle reductions + 8-word smem exchange. Grid (2048).
// ---------------------------------------------------------------------------
__global__ __launch_bounds__(256) void softmax_kernel(int b)
{
    const size_t row = (size_t)b * LSEQ + blockIdx.x;
    const float* p = g_P + row * LSEQ;
    const int t = threadIdx.x;
    const int w = t >> 5;

    __shared__ float red[8];

    float v[8];
    {
        const float4 a = ((const float4*)p)[t * 2];
        const float4 bq = ((const float4*)p)[t * 2 + 1];
        v[0] = a.x; v[1] = a.y; v[2] = a.z; v[3] = a.w;
        v[4] = bq.x; v[5] = bq.y; v[6] = bq.z; v[7] = bq.w;
    }
    float mx = v[0];
#pragma unroll
    for (int i = 1; i < 8; ++i) mx = fmaxf(mx, v[i]);
#pragma unroll
    for (int o = 16; o > 0; o >>= 1)
        mx = fmaxf(mx, __shfl_xor_sync(0xffffffffu, mx, o));
    if ((t & 31) == 0) red[w] = mx;
    __syncthreads();
    float m = red[0];
#pragma unroll
    for (int i = 1; i < 8; ++i) m = fmaxf(m, red[i]);
    __syncthreads();

    float sum = 0.0f;
#pragma unroll
    for (int i = 0; i < 8; ++i) {
        v[i] = __expf(v[i] - m);
        sum += v[i];
    }
#pragma unroll
    for (int o = 16; o > 0; o >>= 1)
        sum += __shfl_xor_sync(0xffffffffu, sum, o);
    if ((t & 31) == 0) red[w] = sum;
    __syncthreads();
    float tot = red[0];
#pragma unroll
    for (int i = 1; i < 8; ++i) tot += red[i];
    const float inv = 1.0f / tot;

    __half h[8];
#pragma unroll
    for (int i = 0; i < 8; ++i) h[i] = __float2half(v[i] * inv);
    *(uint4*)(g_af + row * LSEQ + t * 8) = *(const uint4*)h;
}

// ---------------------------------------------------------------------------
// Kernel 4: AV single-product fp16 HMMA GEMM, one batch. Tile 128x128,
// K-chunk 64, 3-stage cp.async. Grid (4, 16).
// ---------------------------------------------------------------------------
__global__ __launch_bounds__(256, 2) void av_kernel(float* __restrict__ Cout, int b)
{
    extern __shared__ __align__(128) char dsm[];

    constexpr int K       = LSEQ;
    constexpr int NC      = K / 64;        // 32
    constexpr int TILE_B  = 128 * 128;     // 16 KB
    constexpr int STAGE_B = 2 * TILE_B;    // 32 KB

    const int n0 = blockIdx.x * 128;
    const int m0 = blockIdx.y * 128;
    const int t    = threadIdx.x;
    const int lane = t & 31;
    const int wid  = t >> 5;
    const int wm   = wid & 1;
    const int wn   = wid >> 1;

    const __half* pA = g_af  + ((size_t)b * LSEQ + m0) * LSEQ;
    const __half* pB = g_vtf + ((size_t)b * DDIM + n0) * LSEQ;
    float* Cb = Cout + ((size_t)b * LSEQ + m0) * DDIM + n0;

    const uint32_t sb = smem_u32(dsm);

    auto prefetch = [&](int c, int s) {
        const int k0 = c * 64;
        const uint32_t st = sb + s * STAGE_B;
        const __half* gs[2] = { pA + k0, pB + k0 };
#pragma unroll
        for (int tt = 0; tt < 2; ++tt) {
            const uint32_t tb = st + tt * TILE_B;
#pragma unroll
            for (int i = 0; i < 4; ++i) {
                const int li  = t + i * 256;
                const int row = li >> 3;
                const int seg = li & 7;
                CP_ASYNC16(tb + swz128(row, seg), gs[tt] + (size_t)row * LSEQ + seg * 8);
            }
        }
        CP_COMMIT();
    };

    float acc[4][4][4];
#pragma unroll
    for (int mf = 0; mf < 4; ++mf)
#pragma unroll
        for (int nf = 0; nf < 4; ++nf)
#pragma unroll
            for (int i = 0; i < 4; ++i) acc[mf][nf][i] = 0.0f;

    const int lr   = lane & 15;
    const int lseg = lane >> 4;

    prefetch(0, 0);
    prefetch(1, 1);

    int s = 0;
    for (int c = 0; c < NC; ++c) {
        if (c + 1 < NC) { CP_WAITN(1); } else { CP_WAITN(0); }
        __syncthreads();

        const uint32_t sA = sb + s * STAGE_B;
        const uint32_t sB = sA + TILE_B;

#pragma unroll
        for (int ks = 0; ks < 4; ++ks) {
            const int segk = ks * 2 + lseg;
            uint32_t a[4][4], bb[2][4];
#pragma unroll
            for (int mf = 0; mf < 4; ++mf)
                ldsm4(a[mf], sA + swz128(wm * 64 + mf * 16 + lr, segk));
#pragma unroll
            for (int p = 0; p < 2; ++p)
                ldsm4(bb[p], sB + swz128(wn * 32 + p * 16 + lr, segk));
#pragma unroll
            for (int mf = 0; mf < 4; ++mf)
#pragma unroll
                for (int nf = 0; nf < 4; ++nf) {
                    const int p = nf >> 1, s2 = nf & 1;
                    MMA_F16(acc[mf][nf], a[mf], bb[p][s2], bb[p][s2 + 2]);
                }
        }

        if (c + 2 < NC) {
            int s2 = s + 2; if (s2 >= 3) s2 -= 3;
            prefetch(c + 2, s2);
        }
        if (++s == 3) s = 0;
    }

#pragma unroll
    for (int mf = 0; mf < 4; ++mf) {
#pragma unroll
        for (int nf = 0; nf < 4; ++nf) {
            const int r0 = wm * 64 + mf * 16 + (lane >> 2);
            const int cc = wn * 32 + nf * 8 + (lane & 3) * 2;
            float2 v0, v1;
            v0.x = acc[mf][nf][0]; v0.y = acc[mf][nf][1];
            v1.x = acc[mf][nf][2]; v1.y = acc[mf][nf][3];
            *(float2*)&Cb[(size_t)r0 * DDIM + cc]       = v0;
            *(float2*)&Cb[(size_t)(r0 + 8) * DDIM + cc] = v1;
        }
    }
}

// ---------------------------------------------------------------------------
// Launch: per-batch pipeline across two streams.
//   stream 0 (capture stream): split(b) -> qk(b) -> record evQK[b]
//   s1 (high priority):        wait evQK[b] -> softmax(b) -> av(b)
// Streams/events are created fresh each call and intentionally leaked
// (kernel_launch is invoked only a handful of times; no device memory).
// ---------------------------------------------------------------------------
extern "C" void kernel_launch(void* const* d_in, const int* in_sizes, int n_in,
                              void* d_out, int out_size)
{
    const float* x  = (const float*)d_in[0];
    const float* qw = (const float*)d_in[1];
    const float* kw = (const float*)d_in[2];
    const float* vw = (const float*)d_in[3];
    float* out = (float*)d_out;

    constexpr int SMEM = 98304;   // 3 stages x 32 KB
    cudaFuncSetAttribute(qk_kernel, cudaFuncAttributeMaxDynamicSharedMemorySize, SMEM);
    cudaFuncSetAttribute(av_kernel, cudaFuncAttributeMaxDynamicSharedMemorySize, SMEM);

    int prLo = 0, prHi = 0;
    cudaDeviceGetStreamPriorityRange(&prLo, &prHi);
    cudaStream_t s1;
    cudaStreamCreateWithPriority(&s1, cudaStreamNonBlocking, prHi);

    cudaEvent_t evQK[BATCH], evJoin;
    for (int b = 0; b < BATCH; ++b)
        cudaEventCreateWithFlags(&evQK[b], cudaEventDisableTiming);
    cudaEventCreateWithFlags(&evJoin, cudaEventDisableTiming);

    for (int b = 0; b < BATCH; ++b) {
        split_kernel<<<dim3(LSEQ / 64, DDIM / 64), 256>>>(x, qw, kw, vw, b);
        qk_kernel<<<dim3(LSEQ / 128, LSEQ / 128), 256, SMEM>>>(b);
        cudaEventRecord(evQK[b], 0);
        cudaStreamWaitEvent(s1, evQK[b], 0);
        softmax_kernel<<<LSEQ, 256, 0, s1>>>(b);
        av_kernel<<<dim3(DDIM / 128, LSEQ / 128), 256, SMEM, s1>>>(out, b);
    }
    cudaEventRecord(evJoin, s1);
    cudaStreamWaitEvent(0, evJoin, 0);
}

// round 11
// speedup vs baseline: 1.3860x; 1.3860x over previous
#include <cuda_runtime.h>
#include <cuda_bf16.h>
#include <cuda_fp16.h>
#include <cstdint>
#include <math.h>

#define BATCH 8
#define LSEQ  2048
#define DDIM  512

// ---------------------------------------------------------------------------
// Device-global scratch (module-load allocation; no runtime allocs).
// ---------------------------------------------------------------------------
static __device__ float g_P[(size_t)BATCH * LSEQ * LSEQ];                           // 128 MiB logits
static __device__ __align__(128) __nv_bfloat16 g_qh[(size_t)BATCH * LSEQ * DDIM];
static __device__ __align__(128) __nv_bfloat16 g_ql[(size_t)BATCH * LSEQ * DDIM];
static __device__ __align__(128) __nv_bfloat16 g_kh[(size_t)BATCH * LSEQ * DDIM];
static __device__ __align__(128) __nv_bfloat16 g_kl[(size_t)BATCH * LSEQ * DDIM];
static __device__ __align__(128) __half g_vtf[(size_t)BATCH * DDIM * LSEQ];         // v^T fp16 [b][d][j]
static __device__ __align__(128) __half g_af[(size_t)BATCH * LSEQ * LSEQ];          // attn fp16

// ---------------------------------------------------------------------------
// PTX helpers (sm_80+ only; base sm_103 target has no tcgen05)
// ---------------------------------------------------------------------------
__device__ __forceinline__ uint32_t smem_u32(const void* p) {
    uint32_t a;
    asm("{ .reg .u64 t; cvta.to.shared.u64 t, %1; cvt.u32.u64 %0, t; }" : "=r"(a) : "l"(p));
    return a;
}
__device__ __forceinline__ void ldsm4(uint32_t* r, uint32_t addr) {
    asm volatile("ldmatrix.sync.aligned.m8n8.x4.shared.b16 {%0,%1,%2,%3}, [%4];"
                 : "=r"(r[0]), "=r"(r[1]), "=r"(r[2]), "=r"(r[3]) : "r"(addr));
}
#define MMA_BF16(d, a, b0, b1)                                                     \
    asm volatile("mma.sync.aligned.m16n8k16.row.col.f32.bf16.bf16.f32 "            \
                 "{%0,%1,%2,%3},{%4,%5,%6,%7},{%8,%9},{%0,%1,%2,%3};"              \
                 : "+f"((d)[0]), "+f"((d)[1]), "+f"((d)[2]), "+f"((d)[3])          \
                 : "r"((a)[0]), "r"((a)[1]), "r"((a)[2]), "r"((a)[3]),             \
                   "r"(b0), "r"(b1))
#define MMA_F16(d, a, b0, b1)                                                      \
    asm volatile("mma.sync.aligned.m16n8k16.row.col.f32.f16.f16.f32 "              \
                 "{%0,%1,%2,%3},{%4,%5,%6,%7},{%8,%9},{%0,%1,%2,%3};"              \
                 : "+f"((d)[0]), "+f"((d)[1]), "+f"((d)[2]), "+f"((d)[3])          \
                 : "r"((a)[0]), "r"((a)[1]), "r"((a)[2]), "r"((a)[3]),             \
                   "r"(b0), "r"(b1))
#define CP_ASYNC16(dst, src) \
    asm volatile("cp.async.cg.shared.global [%0], [%1], 16;" :: "r"(dst), "l"(src))
#define CP_COMMIT()  asm volatile("cp.async.commit_group;" ::: "memory")
#define CP_WAITN(n)  asm volatile("cp.async.wait_group %0;" :: "n"(n) : "memory")

__device__ __forceinline__ void split2(float v, __nv_bfloat16& h, __nv_bfloat16& l) {
    h = __float2bfloat16(v);
    l = __float2bfloat16(v - __bfloat162float(h));
}

// Swizzle for 64-byte rows (4 x 16B segs): seg ^= (row>>1)&3
__device__ __forceinline__ uint32_t swz64(int row, int seg) {
    return (uint32_t)(row * 64 + ((seg ^ ((row >> 1) & 3)) << 4));
}
// Swizzle for 128-byte rows (8 x 16B segs): seg ^= row&7
__device__ __forceinline__ uint32_t swz128(int row, int seg) {
    return (uint32_t)(row * 128 + ((seg ^ (row & 7)) << 4));
}

// ---------------------------------------------------------------------------
// Kernel 1: split projections. q,k -> bf16 hi/lo [b][i][d]; v -> fp16 single,
// transposed [b][d][j] via smem tile transpose. Block = 64(j) x 64(d).
// ---------------------------------------------------------------------------
__global__ __launch_bounds__(256) void split_kernel(const float* __restrict__ x,
                                                    const float* __restrict__ qw,
                                                    const float* __restrict__ kw,
                                                    const float* __restrict__ vw)
{
    __shared__ __half vf_s[64][66];

    const int b  = blockIdx.z;
    const int j0 = blockIdx.x * 64;
    const int d0 = blockIdx.y * 64;
    const int t  = threadIdx.x;

    union U4 { __nv_bfloat16 h[4]; uint2 u; };

#pragma unroll
    for (int it = 0; it < 4; ++it) {
        const int id = t + it * 256;
        const int r  = id >> 4;
        const int c  = (id & 15) * 4;
        const size_t gx = ((size_t)b * LSEQ + j0 + r) * DDIM + d0 + c;
        const size_t gw = (size_t)(j0 + r) * DDIM + d0 + c;
        const float4 xv = *(const float4*)(x  + gx);
        const float4 q4 = *(const float4*)(qw + gw);
        const float4 k4 = *(const float4*)(kw + gw);
        const float4 v4 = *(const float4*)(vw + gw);

        U4 qh, ql, kh, kl;
        split2(xv.x * q4.x, qh.h[0], ql.h[0]); split2(xv.y * q4.y, qh.h[1], ql.h[1]);
        split2(xv.z * q4.z, qh.h[2], ql.h[2]); split2(xv.w * q4.w, qh.h[3], ql.h[3]);
        split2(xv.x * k4.x, kh.h[0], kl.h[0]); split2(xv.y * k4.y, kh.h[1], kl.h[1]);
        split2(xv.z * k4.z, kh.h[2], kl.h[2]); split2(xv.w * k4.w, kh.h[3], kl.h[3]);
        *(uint2*)(g_qh + gx) = qh.u;  *(uint2*)(g_ql + gx) = ql.u;
        *(uint2*)(g_kh + gx) = kh.u;  *(uint2*)(g_kl + gx) = kl.u;

        vf_s[r][c + 0] = __float2half(xv.x * v4.x);
        vf_s[r][c + 1] = __float2half(xv.y * v4.y);
        vf_s[r][c + 2] = __float2half(xv.z * v4.z);
        vf_s[r][c + 3] = __float2half(xv.w * v4.w);
    }
    __syncthreads();

#pragma unroll
    for (int it = 0; it < 2; ++it) {
        const int id = t + it * 256;
        const int dr = id >> 3;
        const int jg = (id & 7) * 8;
        __half tmp[8];
#pragma unroll
        for (int j = 0; j < 8; ++j) tmp[j] = vf_s[jg + j][dr];
        *(uint4*)(g_vtf + ((size_t)b * DDIM + d0 + dr) * LSEQ + j0 + jg) =
            *(const uint4*)tmp;
    }
}

// ---------------------------------------------------------------------------
// Kernel 2: QK 3-product bf16 HMMA GEMM. P = scale * (Qh+Ql)(Kh+Kl)^T (lo*lo
// dropped). Tile 128x128, K-chunk 32, 3-stage cp.async, 2 CTAs/SM.
// ---------------------------------------------------------------------------
__global__ __launch_bounds__(256, 2) void qk_kernel()
{
    extern __shared__ __align__(128) char dsm[];

    constexpr int K       = DDIM;
    constexpr int NC      = K / 32;        // 16
    constexpr int TILE_B  = 128 * 64;      // 8 KB
    constexpr int STAGE_B = 4 * TILE_B;    // 32 KB
    const float scale = 0.3535533905932738f;

    const int b  = blockIdx.z;
    const int n0 = blockIdx.x * 128;
    const int m0 = blockIdx.y * 128;
    const int t    = threadIdx.x;
    const int lane = t & 31;
    const int wid  = t >> 5;
    const int wm   = wid & 1;
    const int wn   = wid >> 1;

    const __nv_bfloat16* pAh = g_qh + ((size_t)b * LSEQ + m0) * K;
    const __nv_bfloat16* pAl = g_ql + ((size_t)b * LSEQ + m0) * K;
    const __nv_bfloat16* pBh = g_kh + ((size_t)b * LSEQ + n0) * K;
    const __nv_bfloat16* pBl = g_kl + ((size_t)b * LSEQ + n0) * K;
    float* Cb = g_P + ((size_t)b * LSEQ + m0) * LSEQ + n0;

    const uint32_t sb = smem_u32(dsm);

    auto prefetch = [&](int c, int s) {
        const int k0 = c * 32;
        const uint32_t st = sb + s * STAGE_B;
        const __nv_bfloat16* gs[4] = { pAh + k0, pAl + k0, pBh + k0, pBl + k0 };
#pragma unroll
        for (int tt = 0; tt < 4; ++tt) {
            const uint32_t tb = st + tt * TILE_B;
#pragma unroll
            for (int i = 0; i < 2; ++i) {
                const int li  = t + i * 256;
                const int row = li >> 2;
                const int seg = li & 3;
                CP_ASYNC16(tb + swz64(row, seg), gs[tt] + (size_t)row * K + seg * 8);
            }
        }
        CP_COMMIT();
    };

    float acc[4][4][4];
#pragma unroll
    for (int mf = 0; mf < 4; ++mf)
#pragma unroll
        for (int nf = 0; nf < 4; ++nf)
#pragma unroll
            for (int i = 0; i < 4; ++i) acc[mf][nf][i] = 0.0f;

    const int lr   = lane & 15;
    const int lseg = lane >> 4;

    prefetch(0, 0);
    prefetch(1, 1);

    int s = 0;
    for (int c = 0; c < NC; ++c) {
        if (c + 1 < NC) { CP_WAITN(1); } else { CP_WAITN(0); }
        __syncthreads();

        const uint32_t st  = sb + s * STAGE_B;
        const uint32_t sAh = st;
        const uint32_t sAl = st + TILE_B;
        const uint32_t sBh = st + 2 * TILE_B;
        const uint32_t sBl = st + 3 * TILE_B;

#pragma unroll
        for (int ks = 0; ks < 2; ++ks) {
            const int segk = ks * 2 + lseg;
            uint32_t ah[4][4], al[4][4], bh[2][4], bl[2][4];
#pragma unroll
            for (int mf = 0; mf < 4; ++mf) {
                const uint32_t off = swz64(wm * 64 + mf * 16 + lr, segk);
                ldsm4(ah[mf], sAh + off);
                ldsm4(al[mf], sAl + off);
            }
#pragma unroll
            for (int p = 0; p < 2; ++p) {
                const uint32_t off = swz64(wn * 32 + p * 16 + lr, segk);
                ldsm4(bh[p], sBh + off);
                ldsm4(bl[p], sBl + off);
            }
#pragma unroll
            for (int mf = 0; mf < 4; ++mf)
#pragma unroll
                for (int nf = 0; nf < 4; ++nf) {
                    const int p = nf >> 1, s2 = nf & 1;
                    MMA_BF16(acc[mf][nf], ah[mf], bh[p][s2], bh[p][s2 + 2]);
                }
#pragma unroll
            for (int mf = 0; mf < 4; ++mf)
#pragma unroll
                for (int nf = 0; nf < 4; ++nf) {
                    const int p = nf >> 1, s2 = nf & 1;
                    MMA_BF16(acc[mf][nf], al[mf], bh[p][s2], bh[p][s2 + 2]);
                }
#pragma unroll
            for (int mf = 0; mf < 4; ++mf)
#pragma unroll
                for (int nf = 0; nf < 4; ++nf) {
                    const int p = nf >> 1, s2 = nf & 1;
                    MMA_BF16(acc[mf][nf], ah[mf], bl[p][s2], bl[p][s2 + 2]);
                }
        }

        if (c + 2 < NC) {
            int s2 = s + 2; if (s2 >= 3) s2 -= 3;
            prefetch(c + 2, s2);
        }
        if (++s == 3) s = 0;
    }

#pragma unroll
    for (int mf = 0; mf < 4; ++mf) {
#pragma unroll
        for (int nf = 0; nf < 4; ++nf) {
            const int r0 = wm * 64 + mf * 16 + (lane >> 2);
            const int cc = wn * 32 + nf * 8 + (lane & 3) * 2;
            float2 v0, v1;
            v0.x = acc[mf][nf][0] * scale; v0.y = acc[mf][nf][1] * scale;
            v1.x = acc[mf][nf][2] * scale; v1.y = acc[mf][nf][3] * scale;
            *(float2*)&Cb[(size_t)r0 * LSEQ + cc]       = v0;
            *(float2*)&Cb[(size_t)(r0 + 8) * LSEQ + cc] = v1;
        }
    }
}

// ---------------------------------------------------------------------------
// Kernel 3: row softmax over g_P -> fp16 attention g_af.
// Shuffle reductions + 8-word smem exchange (2 barriers total).
// ---------------------------------------------------------------------------
__global__ __launch_bounds__(256) void softmax_kernel()
{
    const size_t row = blockIdx.x;
    const float* p = g_P + row * LSEQ;
    const int t = threadIdx.x;
    const int w = t >> 5;

    __shared__ float red[8];

    float v[8];
    {
        const float4 a = ((const float4*)p)[t * 2];
        const float4 b = ((const float4*)p)[t * 2 + 1];
        v[0] = a.x; v[1] = a.y; v[2] = a.z; v[3] = a.w;
        v[4] = b.x; v[5] = b.y; v[6] = b.z; v[7] = b.w;
    }
    float mx = v[0];
#pragma unroll
    for (int i = 1; i < 8; ++i) mx = fmaxf(mx, v[i]);
#pragma unroll
    for (int o = 16; o > 0; o >>= 1)
        mx = fmaxf(mx, __shfl_xor_sync(0xffffffffu, mx, o));
    if ((t & 31) == 0) red[w] = mx;
    __syncthreads();
    float m = red[0];
#pragma unroll
    for (int i = 1; i < 8; ++i) m = fmaxf(m, red[i]);
    __syncthreads();

    float sum = 0.0f;
#pragma unroll
    for (int i = 0; i < 8; ++i) {
        v[i] = __expf(v[i] - m);
        sum += v[i];
    }
#pragma unroll
    for (int o = 16; o > 0; o >>= 1)
        sum += __shfl_xor_sync(0xffffffffu, sum, o);
    if ((t & 31) == 0) red[w] = sum;
    __syncthreads();
    float tot = red[0];
#pragma unroll
    for (int i = 1; i < 8; ++i) tot += red[i];
    const float inv = 1.0f / tot;

    __half h[8];
#pragma unroll
    for (int i = 0; i < 8; ++i) h[i] = __float2half(v[i] * inv);
    *(uint4*)(g_af + row * LSEQ + t * 8) = *(const uint4*)h;
}

// ---------------------------------------------------------------------------
// Kernel 4: AV single-product fp16 HMMA GEMM.
// Tile 128x128, K-chunk 64 (128-byte rows, SW128), 3-stage cp.async.
// ---------------------------------------------------------------------------
__global__ __launch_bounds__(256, 2) void av_kernel(float* __restrict__ Cout)
{
    extern __shared__ __align__(128) char dsm[];

    constexpr int K       = LSEQ;
    constexpr int NC      = K / 64;        // 32
    constexpr int TILE_B  = 128 * 128;     // 16 KB
    constexpr int STAGE_B = 2 * TILE_B;    // 32 KB

    const int b  = blockIdx.z;
    const int n0 = blockIdx.x * 128;
    const int m0 = blockIdx.y * 128;
    const int t    = threadIdx.x;
    const int lane = t & 31;
    const int wid  = t >> 5;
    const int wm   = wid & 1;
    const int wn   = wid >> 1;

    const __half* pA = g_af  + ((size_t)b * LSEQ + m0) * LSEQ;
    const __half* pB = g_vtf + ((size_t)b * DDIM + n0) * LSEQ;
    float* Cb = Cout + ((size_t)b * LSEQ + m0) * DDIM + n0;

    const uint32_t sb = smem_u32(dsm);

    auto prefetch = [&](int c, int s) {
        const int k0 = c * 64;
        const uint32_t st = sb + s * STAGE_B;
        const __half* gs[2] = { pA + k0, pB + k0 };
#pragma unroll
        for (int tt = 0; tt < 2; ++tt) {
            const uint32_t tb = st + tt * TILE_B;
#pragma unroll
            for (int i = 0; i < 4; ++i) {
                const int li  = t + i * 256;
                const int row = li >> 3;
                const int seg = li & 7;
                CP_ASYNC16(tb + swz128(row, seg), gs[tt] + (size_t)row * LSEQ + seg * 8);
            }
        }
        CP_COMMIT();
    };

    float acc[4][4][4];
#pragma unroll
    for (int mf = 0; mf < 4; ++mf)
#pragma unroll
        for (int nf = 0; nf < 4; ++nf)
#pragma unroll
            for (int i = 0; i < 4; ++i) acc[mf][nf][i] = 0.0f;

    const int lr   = lane & 15;
    const int lseg = lane >> 4;

    prefetch(0, 0);
    prefetch(1, 1);

    int s = 0;
    for (int c = 0; c < NC; ++c) {
        if (c + 1 < NC) { CP_WAITN(1); } else { CP_WAITN(0); }
        __syncthreads();

        const uint32_t sA = sb + s * STAGE_B;
        const uint32_t sB = sA + TILE_B;

#pragma unroll
        for (int ks = 0; ks < 4; ++ks) {
            const int segk = ks * 2 + lseg;
            uint32_t a[4][4], bb[2][4];
#pragma unroll
            for (int mf = 0; mf < 4; ++mf)
                ldsm4(a[mf], sA + swz128(wm * 64 + mf * 16 + lr, segk));
#pragma unroll
            for (int p = 0; p < 2; ++p)
                ldsm4(bb[p], sB + swz128(wn * 32 + p * 16 + lr, segk));
#pragma unroll
            for (int mf = 0; mf < 4; ++mf)
#pragma unroll
                for (int nf = 0; nf < 4; ++nf) {
                    const int p = nf >> 1, s2 = nf & 1;
                    MMA_F16(acc[mf][nf], a[mf], bb[p][s2], bb[p][s2 + 2]);
                }
        }

        if (c + 2 < NC) {
            int s2 = s + 2; if (s2 >= 3) s2 -= 3;
            prefetch(c + 2, s2);
        }
        if (++s == 3) s = 0;
    }

#pragma unroll
    for (int mf = 0; mf < 4; ++mf) {
#pragma unroll
        for (int nf = 0; nf < 4; ++nf) {
            const int r0 = wm * 64 + mf * 16 + (lane >> 2);
            const int cc = wn * 32 + nf * 8 + (lane & 3) * 2;
            float2 v0, v1;
            v0.x = acc[mf][nf][0]; v0.y = acc[mf][nf][1];
            v1.x = acc[mf][nf][2]; v1.y = acc[mf][nf][3];
            *(float2*)&Cb[(size_t)r0 * DDIM + cc]       = v0;
            *(float2*)&Cb[(size_t)(r0 + 8) * DDIM + cc] = v1;
        }
    }
}

// ---------------------------------------------------------------------------
extern "C" void kernel_launch(void* const* d_in, const int* in_sizes, int n_in,
                              void* d_out, int out_size)
{
    const float* x  = (const float*)d_in[0];
    const float* qw = (const float*)d_in[1];
    const float* kw = (const float*)d_in[2];
    const float* vw = (const float*)d_in[3];
    float* out = (float*)d_out;

    constexpr int SMEM = 98304;   // 3 stages x 32 KB
    cudaFuncSetAttribute(qk_kernel, cudaFuncAttributeMaxDynamicSharedMemorySize, SMEM);
    cudaFuncSetAttribute(av_kernel, cudaFuncAttributeMaxDynamicSharedMemorySize, SMEM);

    split_kernel<<<dim3(LSEQ / 64, DDIM / 64, BATCH), 256>>>(x, qw, kw, vw);

    qk_kernel<<<dim3(LSEQ / 128, LSEQ / 128, BATCH), 256, SMEM>>>();

    softmax_kernel<<<BATCH * LSEQ, 256>>>();

    av_kernel<<<dim3(DDIM / 128, LSEQ / 128, BATCH), 256, SMEM>>>(out);
}

// round 12
// speedup vs baseline: 1.6498x; 1.1903x over previous
#include <cuda_runtime.h>
#include <cuda_bf16.h>
#include <cuda_fp16.h>
#include <cstdint>
#include <math.h>

#define BATCH 8
#define LSEQ  2048
#define DDIM  512

// ---------------------------------------------------------------------------
// Device-global scratch (module-load allocation; no runtime allocs).
// ---------------------------------------------------------------------------
static __device__ float g_P[(size_t)BATCH * LSEQ * LSEQ];                       // 128 MiB logits
static __device__ __align__(128) __half g_qh[(size_t)BATCH * LSEQ * DDIM];      // q fp16 hi
static __device__ __align__(128) __half g_ql[(size_t)BATCH * LSEQ * DDIM];      // q fp16 lo
static __device__ __align__(128) __half g_kf[(size_t)BATCH * LSEQ * DDIM];      // k fp16
static __device__ __align__(128) __half g_vtf[(size_t)BATCH * DDIM * LSEQ];     // v^T fp16 [b][d][j]
static __device__ __align__(128) __half g_af[(size_t)BATCH * LSEQ * LSEQ];      // attn fp16

// ---------------------------------------------------------------------------
// PTX helpers (sm_80+ only; base sm_103 target has no tcgen05)
// ---------------------------------------------------------------------------
__device__ __forceinline__ uint32_t smem_u32(const void* p) {
    uint32_t a;
    asm("{ .reg .u64 t; cvta.to.shared.u64 t, %1; cvt.u32.u64 %0, t; }" : "=r"(a) : "l"(p));
    return a;
}
__device__ __forceinline__ void ldsm4(uint32_t* r, uint32_t addr) {
    asm volatile("ldmatrix.sync.aligned.m8n8.x4.shared.b16 {%0,%1,%2,%3}, [%4];"
                 : "=r"(r[0]), "=r"(r[1]), "=r"(r[2]), "=r"(r[3]) : "r"(addr));
}
#define MMA_F16(d, a, b0, b1)                                                      \
    asm volatile("mma.sync.aligned.m16n8k16.row.col.f32.f16.f16.f32 "              \
                 "{%0,%1,%2,%3},{%4,%5,%6,%7},{%8,%9},{%0,%1,%2,%3};"              \
                 : "+f"((d)[0]), "+f"((d)[1]), "+f"((d)[2]), "+f"((d)[3])          \
                 : "r"((a)[0]), "r"((a)[1]), "r"((a)[2]), "r"((a)[3]),             \
                   "r"(b0), "r"(b1))
#define CP_ASYNC16(dst, src) \
    asm volatile("cp.async.cg.shared.global [%0], [%1], 16;" :: "r"(dst), "l"(src))
#define CP_COMMIT()  asm volatile("cp.async.commit_group;" ::: "memory")
#define CP_WAITN(n)  asm volatile("cp.async.wait_group %0;" :: "n"(n) : "memory")

__device__ __forceinline__ void split2h(float v, __half& h, __half& l) {
    h = __float2half(v);
    l = __float2half(v - __half2float(h));
}

// Swizzle for 64-byte rows (4 x 16B segs): seg ^= (row>>1)&3
__device__ __forceinline__ uint32_t swz64(int row, int seg) {
    return (uint32_t)(row * 64 + ((seg ^ ((row >> 1) & 3)) << 4));
}
// Swizzle for 128-byte rows (8 x 16B segs): seg ^= row&7
__device__ __forceinline__ uint32_t swz128(int row, int seg) {
    return (uint32_t)(row * 128 + ((seg ^ (row & 7)) << 4));
}

// ---------------------------------------------------------------------------
// Kernel 1: split projections. q -> fp16 hi/lo [b][i][d]; k -> fp16 single;
// v -> fp16 single, transposed [b][d][j]. Block = 64(j) x 64(d).
// ---------------------------------------------------------------------------
__global__ __launch_bounds__(256) void split_kernel(const float* __restrict__ x,
                                                    const float* __restrict__ qw,
                                                    const float* __restrict__ kw,
                                                    const float* __restrict__ vw)
{
    __shared__ __half vf_s[64][66];

    const int b  = blockIdx.z;
    const int j0 = blockIdx.x * 64;
    const int d0 = blockIdx.y * 64;
    const int t  = threadIdx.x;

    union U4 { __half h[4]; uint2 u; };

#pragma unroll
    for (int it = 0; it < 4; ++it) {
        const int id = t + it * 256;
        const int r  = id >> 4;
        const int c  = (id & 15) * 4;
        const size_t gx = ((size_t)b * LSEQ + j0 + r) * DDIM + d0 + c;
        const size_t gw = (size_t)(j0 + r) * DDIM + d0 + c;
        const float4 xv = *(const float4*)(x  + gx);
        const float4 q4 = *(const float4*)(qw + gw);
        const float4 k4 = *(const float4*)(kw + gw);
        const float4 v4 = *(const float4*)(vw + gw);

        U4 qh, ql, kf;
        split2h(xv.x * q4.x, qh.h[0], ql.h[0]); split2h(xv.y * q4.y, qh.h[1], ql.h[1]);
        split2h(xv.z * q4.z, qh.h[2], ql.h[2]); split2h(xv.w * q4.w, qh.h[3], ql.h[3]);
        kf.h[0] = __float2half(xv.x * k4.x);
        kf.h[1] = __float2half(xv.y * k4.y);
        kf.h[2] = __float2half(xv.z * k4.z);
        kf.h[3] = __float2half(xv.w * k4.w);
        *(uint2*)(g_qh + gx) = qh.u;
        *(uint2*)(g_ql + gx) = ql.u;
        *(uint2*)(g_kf + gx) = kf.u;

        vf_s[r][c + 0] = __float2half(xv.x * v4.x);
        vf_s[r][c + 1] = __float2half(xv.y * v4.y);
        vf_s[r][c + 2] = __float2half(xv.z * v4.z);
        vf_s[r][c + 3] = __float2half(xv.w * v4.w);
    }
    __syncthreads();

#pragma unroll
    for (int it = 0; it < 2; ++it) {
        const int id = t + it * 256;
        const int dr = id >> 3;
        const int jg = (id & 7) * 8;
        __half tmp[8];
#pragma unroll
        for (int j = 0; j < 8; ++j) tmp[j] = vf_s[jg + j][dr];
        *(uint4*)(g_vtf + ((size_t)b * DDIM + d0 + dr) * LSEQ + j0 + jg) =
            *(const uint4*)tmp;
    }
}

// ---------------------------------------------------------------------------
// Kernel 2: QK 2-product fp16 HMMA GEMM. P = scale * (Qhi + Qlo) K^T.
// Tile 128x128, K-chunk 32, 3 tiles/stage (qh, ql, kf), 3-stage cp.async,
// 2 CTAs/SM.
// ---------------------------------------------------------------------------
__global__ __launch_bounds__(256, 2) void qk_kernel()
{
    extern __shared__ __align__(128) char dsm[];

    constexpr int K       = DDIM;
    constexpr int NC      = K / 32;        // 16
    constexpr int TILE_B  = 128 * 64;      // 8 KB
    constexpr int STAGE_B = 3 * TILE_B;    // 24 KB
    const float scale = 0.3535533905932738f;

    const int b  = blockIdx.z;
    const int n0 = blockIdx.x * 128;
    const int m0 = blockIdx.y * 128;
    const int t    = threadIdx.x;
    const int lane = t & 31;
    const int wid  = t >> 5;
    const int wm   = wid & 1;
    const int wn   = wid >> 1;

    const __half* pAh = g_qh + ((size_t)b * LSEQ + m0) * K;
    const __half* pAl = g_ql + ((size_t)b * LSEQ + m0) * K;
    const __half* pB  = g_kf + ((size_t)b * LSEQ + n0) * K;
    float* Cb = g_P + ((size_t)b * LSEQ + m0) * LSEQ + n0;

    const uint32_t sb = smem_u32(dsm);

    auto prefetch = [&](int c, int s) {
        const int k0 = c * 32;
        const uint32_t st = sb + s * STAGE_B;
        const __half* gs[3] = { pAh + k0, pAl + k0, pB + k0 };
#pragma unroll
        for (int tt = 0; tt < 3; ++tt) {
            const uint32_t tb = st + tt * TILE_B;
#pragma unroll
            for (int i = 0; i < 2; ++i) {
                const int li  = t + i * 256;
                const int row = li >> 2;
                const int seg = li & 3;
                CP_ASYNC16(tb + swz64(row, seg), gs[tt] + (size_t)row * K + seg * 8);
            }
        }
        CP_COMMIT();
    };

    float acc[4][4][4];
#pragma unroll
    for (int mf = 0; mf < 4; ++mf)
#pragma unroll
        for (int nf = 0; nf < 4; ++nf)
#pragma unroll
            for (int i = 0; i < 4; ++i) acc[mf][nf][i] = 0.0f;

    const int lr   = lane & 15;
    const int lseg = lane >> 4;

    prefetch(0, 0);
    prefetch(1, 1);

    int s = 0;
    for (int c = 0; c < NC; ++c) {
        if (c + 1 < NC) { CP_WAITN(1); } else { CP_WAITN(0); }
        __syncthreads();

        const uint32_t st  = sb + s * STAGE_B;
        const uint32_t sAh = st;
        const uint32_t sAl = st + TILE_B;
        const uint32_t sBf = st + 2 * TILE_B;

#pragma unroll
        for (int ks = 0; ks < 2; ++ks) {
            const int segk = ks * 2 + lseg;
            uint32_t ah[4][4], al[4][4], bf[2][4];
#pragma unroll
            for (int mf = 0; mf < 4; ++mf) {
                const uint32_t off = swz64(wm * 64 + mf * 16 + lr, segk);
                ldsm4(ah[mf], sAh + off);
                ldsm4(al[mf], sAl + off);
            }
#pragma unroll
            for (int p = 0; p < 2; ++p) {
                const uint32_t off = swz64(wn * 32 + p * 16 + lr, segk);
                ldsm4(bf[p], sBf + off);
            }
#pragma unroll
            for (int mf = 0; mf < 4; ++mf)
#pragma unroll
                for (int nf = 0; nf < 4; ++nf) {
                    const int p = nf >> 1, s2 = nf & 1;
                    MMA_F16(acc[mf][nf], ah[mf], bf[p][s2], bf[p][s2 + 2]);
                }
#pragma unroll
            for (int mf = 0; mf < 4; ++mf)
#pragma unroll
                for (int nf = 0; nf < 4; ++nf) {
                    const int p = nf >> 1, s2 = nf & 1;
                    MMA_F16(acc[mf][nf], al[mf], bf[p][s2], bf[p][s2 + 2]);
                }
        }

        if (c + 2 < NC) {
            int s2 = s + 2; if (s2 >= 3) s2 -= 3;
            prefetch(c + 2, s2);
        }
        if (++s == 3) s = 0;
    }

#pragma unroll
    for (int mf = 0; mf < 4; ++mf) {
#pragma unroll
        for (int nf = 0; nf < 4; ++nf) {
            const int r0 = wm * 64 + mf * 16 + (lane >> 2);
            const int cc = wn * 32 + nf * 8 + (lane & 3) * 2;
            float2 v0, v1;
            v0.x = acc[mf][nf][0] * scale; v0.y = acc[mf][nf][1] * scale;
            v1.x = acc[mf][nf][2] * scale; v1.y = acc[mf][nf][3] * scale;
            *(float2*)&Cb[(size_t)r0 * LSEQ + cc]       = v0;
            *(float2*)&Cb[(size_t)(r0 + 8) * LSEQ + cc] = v1;
        }
    }
}

// ---------------------------------------------------------------------------
// Kernel 3: row softmax over g_P -> fp16 attention g_af, for HALF the rows.
// h = 0: rows [0, 4*LSEQ); h = 1: rows [4*LSEQ, 8*LSEQ). Grid 4*LSEQ.
// ---------------------------------------------------------------------------
__global__ __launch_bounds__(256) void softmax_kernel(int h)
{
    const size_t row = (size_t)h * (BATCH / 2) * LSEQ + blockIdx.x;
    const float* p = g_P + row * LSEQ;
    const int t = threadIdx.x;
    const int w = t >> 5;

    __shared__ float red[8];

    float v[8];
    {
        const float4 a = ((const float4*)p)[t * 2];
        const float4 b = ((const float4*)p)[t * 2 + 1];
        v[0] = a.x; v[1] = a.y; v[2] = a.z; v[3] = a.w;
        v[4] = b.x; v[5] = b.y; v[6] = b.z; v[7] = b.w;
    }
    float mx = v[0];
#pragma unroll
    for (int i = 1; i < 8; ++i) mx = fmaxf(mx, v[i]);
#pragma unroll
    for (int o = 16; o > 0; o >>= 1)
        mx = fmaxf(mx, __shfl_xor_sync(0xffffffffu, mx, o));
    if ((t & 31) == 0) red[w] = mx;
    __syncthreads();
    float m = red[0];
#pragma unroll
    for (int i = 1; i < 8; ++i) m = fmaxf(m, red[i]);
    __syncthreads();

    float sum = 0.0f;
#pragma unroll
    for (int i = 0; i < 8; ++i) {
        v[i] = __expf(v[i] - m);
        sum += v[i];
    }
#pragma unroll
    for (int o = 16; o > 0; o >>= 1)
        sum += __shfl_xor_sync(0xffffffffu, sum, o);
    if ((t & 31) == 0) red[w] = sum;
    __syncthreads();
    float tot = red[0];
#pragma unroll
    for (int i = 1; i < 8; ++i) tot += red[i];
    const float inv = 1.0f / tot;

    __half hh[8];
#pragma unroll
    for (int i = 0; i < 8; ++i) hh[i] = __float2half(v[i] * inv);
    *(uint4*)(g_af + row * LSEQ + t * 8) = *(const uint4*)hh;
}

// ---------------------------------------------------------------------------
// Kernel 4: AV single-product fp16 HMMA GEMM for HALF the batches.
// Tile 128x128, K-chunk 64, 3-stage cp.async. Grid (4, 16, 4) = 256 CTAs
// (single full wave at 2 CTAs/SM).
// ---------------------------------------------------------------------------
__global__ __launch_bounds__(256, 2) void av_kernel(float* __restrict__ Cout, int h)
{
    extern __shared__ __align__(128) char dsm[];

    constexpr int K       = LSEQ;
    constexpr int NC      = K / 64;        // 32
    constexpr int TILE_B  = 128 * 128;     // 16 KB
    constexpr int STAGE_B = 2 * TILE_B;    // 32 KB

    const int b  = h * (BATCH / 2) + blockIdx.z;
    const int n0 = blockIdx.x * 128;
    const int m0 = blockIdx.y * 128;
    const int t    = threadIdx.x;
    const int lane = t & 31;
    const int wid  = t >> 5;
    const int wm   = wid & 1;
    const int wn   = wid >> 1;

    const __half* pA = g_af  + ((size_t)b * LSEQ + m0) * LSEQ;
    const __half* pB = g_vtf + ((size_t)b * DDIM + n0) * LSEQ;
    float* Cb = Cout + ((size_t)b * LSEQ + m0) * DDIM + n0;

    const uint32_t sb = smem_u32(dsm);

    auto prefetch = [&](int c, int s) {
        const int k0 = c * 64;
        const uint32_t st = sb + s * STAGE_B;
        const __half* gs[2] = { pA + k0, pB + k0 };
#pragma unroll
        for (int tt = 0; tt < 2; ++tt) {
            const uint32_t tb = st + tt * TILE_B;
#pragma unroll
            for (int i = 0; i < 4; ++i) {
                const int li  = t + i * 256;
                const int row = li >> 3;
                const int seg = li & 7;
                CP_ASYNC16(tb + swz128(row, seg), gs[tt] + (size_t)row * LSEQ + seg * 8);
            }
        }
        CP_COMMIT();
    };

    float acc[4][4][4];
#pragma unroll
    for (int mf = 0; mf < 4; ++mf)
#pragma unroll
        for (int nf = 0; nf < 4; ++nf)
#pragma unroll
            for (int i = 0; i < 4; ++i) acc[mf][nf][i] = 0.0f;

    const int lr   = lane & 15;
    const int lseg = lane >> 4;

    prefetch(0, 0);
    prefetch(1, 1);

    int s = 0;
    for (int c = 0; c < NC; ++c) {
        if (c + 1 < NC) { CP_WAITN(1); } else { CP_WAITN(0); }
        __syncthreads();

        const uint32_t sA = sb + s * STAGE_B;
        const uint32_t sB = sA + TILE_B;

#pragma unroll
        for (int ks = 0; ks < 4; ++ks) {
            const int segk = ks * 2 + lseg;
            uint32_t a[4][4], bb[2][4];
#pragma unroll
            for (int mf = 0; mf < 4; ++mf)
                ldsm4(a[mf], sA + swz128(wm * 64 + mf * 16 + lr, segk));
#pragma unroll
            for (int p = 0; p < 2; ++p)
                ldsm4(bb[p], sB + swz128(wn * 32 + p * 16 + lr, segk));
#pragma unroll
            for (int mf = 0; mf < 4; ++mf)
#pragma unroll
                for (int nf = 0; nf < 4; ++nf) {
                    const int p = nf >> 1, s2 = nf & 1;
                    MMA_F16(acc[mf][nf], a[mf], bb[p][s2], bb[p][s2 + 2]);
                }
        }

        if (c + 2 < NC) {
            int s2 = s + 2; if (s2 >= 3) s2 -= 3;
            prefetch(c + 2, s2);
        }
        if (++s == 3) s = 0;
    }

#pragma unroll
    for (int mf = 0; mf < 4; ++mf) {
#pragma unroll
        for (int nf = 0; nf < 4; ++nf) {
            const int r0 = wm * 64 + mf * 16 + (lane >> 2);
            const int cc = wn * 32 + nf * 8 + (lane & 3) * 2;
            float2 v0, v1;
            v0.x = acc[mf][nf][0]; v0.y = acc[mf][nf][1];
            v1.x = acc[mf][nf][2]; v1.y = acc[mf][nf][3];
            *(float2*)&Cb[(size_t)r0 * DDIM + cc]       = v0;
            *(float2*)&Cb[(size_t)(r0 + 8) * DDIM + cc] = v1;
        }
    }
}

// ---------------------------------------------------------------------------
// Launch. Overlap: sm_h0 -> [AV_h0 || sm_h1(stream s1)] -> AV_h1.
// Streams/events created per call and intentionally leaked (no device mem).
// ---------------------------------------------------------------------------
extern "C" void kernel_launch(void* const* d_in, const int* in_sizes, int n_in,
                              void* d_out, int out_size)
{
    const float* x  = (const float*)d_in[0];
    const float* qw = (const float*)d_in[1];
    const float* kw = (const float*)d_in[2];
    const float* vw = (const float*)d_in[3];
    float* out = (float*)d_out;

    constexpr int SMEM_QK = 73728;   // 3 stages x 24 KB
    constexpr int SMEM_AV = 98304;   // 3 stages x 32 KB
    cudaFuncSetAttribute(qk_kernel, cudaFuncAttributeMaxDynamicSharedMemorySize, SMEM_QK);
    cudaFuncSetAttribute(av_kernel, cudaFuncAttributeMaxDynamicSharedMemorySize, SMEM_AV);

    cudaStream_t s1;
    cudaStreamCreateWithFlags(&s1, cudaStreamNonBlocking);
    cudaEvent_t e0, e1;
    cudaEventCreateWithFlags(&e0, cudaEventDisableTiming);
    cudaEventCreateWithFlags(&e1, cudaEventDisableTiming);

    split_kernel<<<dim3(LSEQ / 64, DDIM / 64, BATCH), 256>>>(x, qw, kw, vw);

    qk_kernel<<<dim3(LSEQ / 128, LSEQ / 128, BATCH), 256, SMEM_QK>>>();

    // softmax half 0 on capture stream; half 1 forked to s1
    softmax_kernel<<<(BATCH / 2) * LSEQ, 256>>>(0);
    cudaEventRecord(e0, 0);
    cudaStreamWaitEvent(s1, e0, 0);
    softmax_kernel<<<(BATCH / 2) * LSEQ, 256, 0, s1>>>(1);
    cudaEventRecord(e1, s1);

    // AV half 0 overlaps sm half 1; AV half 1 after join
    av_kernel<<<dim3(DDIM / 128, LSEQ / 128, BATCH / 2), 256, SMEM_AV>>>(out, 0);
    cudaStreamWaitEvent(0, e1, 0);
    av_kernel<<<dim3(DDIM / 128, LSEQ / 128, BATCH / 2), 256, SMEM_AV>>>(out, 1);
}

// round 13
// speedup vs baseline: 1.6591x; 1.0056x over previous
#include <cuda_runtime.h>
#include <cuda_bf16.h>
#include <cuda_fp16.h>
#include <cstdint>
#include <math.h>

#define BATCH 8
#define LSEQ  2048
#define DDIM  512

// ---------------------------------------------------------------------------
// Device-global scratch (module-load allocation; no runtime allocs).
// ---------------------------------------------------------------------------
static __device__ float g_P[(size_t)BATCH * LSEQ * LSEQ];                       // 128 MiB logits
static __device__ __align__(128) __half g_qh[(size_t)BATCH * LSEQ * DDIM];      // q fp16 hi
static __device__ __align__(128) __half g_ql[(size_t)BATCH * LSEQ * DDIM];      // q fp16 lo
static __device__ __align__(128) __half g_kf[(size_t)BATCH * LSEQ * DDIM];      // k fp16
static __device__ __align__(128) __half g_vtf[(size_t)BATCH * DDIM * LSEQ];     // v^T fp16 [b][d][j]
static __device__ __align__(128) __half g_af[(size_t)BATCH * LSEQ * LSEQ];      // attn fp16

// ---------------------------------------------------------------------------
// PTX helpers (sm_80+ only; base sm_103 target has no tcgen05)
// ---------------------------------------------------------------------------
__device__ __forceinline__ uint32_t smem_u32(const void* p) {
    uint32_t a;
    asm("{ .reg .u64 t; cvta.to.shared.u64 t, %1; cvt.u32.u64 %0, t; }" : "=r"(a) : "l"(p));
    return a;
}
__device__ __forceinline__ void ldsm4(uint32_t* r, uint32_t addr) {
    asm volatile("ldmatrix.sync.aligned.m8n8.x4.shared.b16 {%0,%1,%2,%3}, [%4];"
                 : "=r"(r[0]), "=r"(r[1]), "=r"(r[2]), "=r"(r[3]) : "r"(addr));
}
#define MMA_F16(d, a, b0, b1)                                                      \
    asm volatile("mma.sync.aligned.m16n8k16.row.col.f32.f16.f16.f32 "              \
                 "{%0,%1,%2,%3},{%4,%5,%6,%7},{%8,%9},{%0,%1,%2,%3};"              \
                 : "+f"((d)[0]), "+f"((d)[1]), "+f"((d)[2]), "+f"((d)[3])          \
                 : "r"((a)[0]), "r"((a)[1]), "r"((a)[2]), "r"((a)[3]),             \
                   "r"(b0), "r"(b1))
#define CP_ASYNC16(dst, src) \
    asm volatile("cp.async.cg.shared.global [%0], [%1], 16;" :: "r"(dst), "l"(src))
#define CP_COMMIT()  asm volatile("cp.async.commit_group;" ::: "memory")
#define CP_WAITN(n)  asm volatile("cp.async.wait_group %0;" :: "n"(n) : "memory")

// streaming float4 load (evict-first: P is read exactly once)
__device__ __forceinline__ float4 ldg_cs4(const float4* p) {
    float4 v;
    asm volatile("ld.global.cs.v4.f32 {%0,%1,%2,%3}, [%4];"
                 : "=f"(v.x), "=f"(v.y), "=f"(v.z), "=f"(v.w) : "l"(p));
    return v;
}

__device__ __forceinline__ void split2h(float v, __half& h, __half& l) {
    h = __float2half(v);
    l = __float2half(v - __half2float(h));
}

// Swizzle for 64-byte rows (4 x 16B segs): seg ^= (row>>1)&3
__device__ __forceinline__ uint32_t swz64(int row, int seg) {
    return (uint32_t)(row * 64 + ((seg ^ ((row >> 1) & 3)) << 4));
}
// Swizzle for 128-byte rows (8 x 16B segs): seg ^= row&7
__device__ __forceinline__ uint32_t swz128(int row, int seg) {
    return (uint32_t)(row * 128 + ((seg ^ (row & 7)) << 4));
}

// ---------------------------------------------------------------------------
// Kernel 1a: q -> fp16 hi/lo, k -> fp16. Pure streaming (no smem).
// One 128-thread block per (b, i) row pair region; grid (LSEQ/2, BATCH),
// each block covers 2 rows x 512 cols via float4.
// ---------------------------------------------------------------------------
__global__ __launch_bounds__(256) void split_qk_kernel(const float* __restrict__ x,
                                                       const float* __restrict__ qw,
                                                       const float* __restrict__ kw)
{
    const int b  = blockIdx.y;
    const int i0 = blockIdx.x * 2;          // 2 rows per block
    const int t  = threadIdx.x;             // 256 threads -> 2 rows x 128 f4-chunks
    const int r  = t >> 7;                  // 0..1
    const int c  = (t & 127) * 4;           // 0..508

    const size_t gx = ((size_t)b * LSEQ + i0 + r) * DDIM + c;
    const size_t gw = (size_t)(i0 + r) * DDIM + c;
    const float4 xv = *(const float4*)(x  + gx);
    const float4 q4 = *(const float4*)(qw + gw);
    const float4 k4 = *(const float4*)(kw + gw);

    union U4 { __half h[4]; uint2 u; };
    U4 qh, ql, kf;
    split2h(xv.x * q4.x, qh.h[0], ql.h[0]);
    split2h(xv.y * q4.y, qh.h[1], ql.h[1]);
    split2h(xv.z * q4.z, qh.h[2], ql.h[2]);
    split2h(xv.w * q4.w, qh.h[3], ql.h[3]);
    kf.h[0] = __float2half(xv.x * k4.x);
    kf.h[1] = __float2half(xv.y * k4.y);
    kf.h[2] = __float2half(xv.z * k4.z);
    kf.h[3] = __float2half(xv.w * k4.w);
    *(uint2*)(g_qh + gx) = qh.u;
    *(uint2*)(g_ql + gx) = ql.u;
    *(uint2*)(g_kf + gx) = kf.u;
}

// ---------------------------------------------------------------------------
// Kernel 1b: v = x*vw -> fp16, transposed [b][d][j]. Block = 64(j) x 64(d).
// Runs on a side stream, overlapped with the (tensor-bound) QK GEMM.
// ---------------------------------------------------------------------------
__global__ __launch_bounds__(256) void split_v_kernel(const float* __restrict__ x,
                                                      const float* __restrict__ vw)
{
    __shared__ __half vf_s[64][66];

    const int b  = blockIdx.z;
    const int j0 = blockIdx.x * 64;
    const int d0 = blockIdx.y * 64;
    const int t  = threadIdx.x;

#pragma unroll
    for (int it = 0; it < 4; ++it) {
        const int id = t + it * 256;
        const int r  = id >> 4;
        const int c  = (id & 15) * 4;
        const size_t gx = ((size_t)b * LSEQ + j0 + r) * DDIM + d0 + c;
        const size_t gw = (size_t)(j0 + r) * DDIM + d0 + c;
        const float4 xv = *(const float4*)(x  + gx);
        const float4 v4 = *(const float4*)(vw + gw);
        vf_s[r][c + 0] = __float2half(xv.x * v4.x);
        vf_s[r][c + 1] = __float2half(xv.y * v4.y);
        vf_s[r][c + 2] = __float2half(xv.z * v4.z);
        vf_s[r][c + 3] = __float2half(xv.w * v4.w);
    }
    __syncthreads();

#pragma unroll
    for (int it = 0; it < 2; ++it) {
        const int id = t + it * 256;
        const int dr = id >> 3;
        const int jg = (id & 7) * 8;
        __half tmp[8];
#pragma unroll
        for (int j = 0; j < 8; ++j) tmp[j] = vf_s[jg + j][dr];
        *(uint4*)(g_vtf + ((size_t)b * DDIM + d0 + dr) * LSEQ + j0 + jg) =
            *(const uint4*)tmp;
    }
}

// ---------------------------------------------------------------------------
// Kernel 2: QK 2-product fp16 HMMA GEMM. P = scale * (Qhi + Qlo) K^T.
// Tile 128x128, K-chunk 32, 3 tiles/stage, 3-stage cp.async, 2 CTAs/SM.
// ---------------------------------------------------------------------------
__global__ __launch_bounds__(256, 2) void qk_kernel()
{
    extern __shared__ __align__(128) char dsm[];

    constexpr int K       = DDIM;
    constexpr int NC      = K / 32;        // 16
    constexpr int TILE_B  = 128 * 64;      // 8 KB
    constexpr int STAGE_B = 3 * TILE_B;    // 24 KB
    const float scale = 0.3535533905932738f;

    const int b  = blockIdx.z;
    const int n0 = blockIdx.x * 128;
    const int m0 = blockIdx.y * 128;
    const int t    = threadIdx.x;
    const int lane = t & 31;
    const int wid  = t >> 5;
    const int wm   = wid & 1;
    const int wn   = wid >> 1;

    const __half* pAh = g_qh + ((size_t)b * LSEQ + m0) * K;
    const __half* pAl = g_ql + ((size_t)b * LSEQ + m0) * K;
    const __half* pB  = g_kf + ((size_t)b * LSEQ + n0) * K;
    float* Cb = g_P + ((size_t)b * LSEQ + m0) * LSEQ + n0;

    const uint32_t sb = smem_u32(dsm);

    auto prefetch = [&](int c, int s) {
        const int k0 = c * 32;
        const uint32_t st = sb + s * STAGE_B;
        const __half* gs[3] = { pAh + k0, pAl + k0, pB + k0 };
#pragma unroll
        for (int tt = 0; tt < 3; ++tt) {
            const uint32_t tb = st + tt * TILE_B;
#pragma unroll
            for (int i = 0; i < 2; ++i) {
                const int li  = t + i * 256;
                const int row = li >> 2;
                const int seg = li & 3;
                CP_ASYNC16(tb + swz64(row, seg), gs[tt] + (size_t)row * K + seg * 8);
            }
        }
        CP_COMMIT();
    };

    float acc[4][4][4];
#pragma unroll
    for (int mf = 0; mf < 4; ++mf)
#pragma unroll
        for (int nf = 0; nf < 4; ++nf)
#pragma unroll
            for (int i = 0; i < 4; ++i) acc[mf][nf][i] = 0.0f;

    const int lr   = lane & 15;
    const int lseg = lane >> 4;

    prefetch(0, 0);
    prefetch(1, 1);

    int s = 0;
    for (int c = 0; c < NC; ++c) {
        if (c + 1 < NC) { CP_WAITN(1); } else { CP_WAITN(0); }
        __syncthreads();

        const uint32_t st  = sb + s * STAGE_B;
        const uint32_t sAh = st;
        const uint32_t sAl = st + TILE_B;
        const uint32_t sBf = st + 2 * TILE_B;

#pragma unroll
        for (int ks = 0; ks < 2; ++ks) {
            const int segk = ks * 2 + lseg;
            uint32_t ah[4][4], al[4][4], bf[2][4];
#pragma unroll
            for (int mf = 0; mf < 4; ++mf) {
                const uint32_t off = swz64(wm * 64 + mf * 16 + lr, segk);
                ldsm4(ah[mf], sAh + off);
                ldsm4(al[mf], sAl + off);
            }
#pragma unroll
            for (int p = 0; p < 2; ++p) {
                const uint32_t off = swz64(wn * 32 + p * 16 + lr, segk);
                ldsm4(bf[p], sBf + off);
            }
#pragma unroll
            for (int mf = 0; mf < 4; ++mf)
#pragma unroll
                for (int nf = 0; nf < 4; ++nf) {
                    const int p = nf >> 1, s2 = nf & 1;
                    MMA_F16(acc[mf][nf], ah[mf], bf[p][s2], bf[p][s2 + 2]);
                }
#pragma unroll
            for (int mf = 0; mf < 4; ++mf)
#pragma unroll
                for (int nf = 0; nf < 4; ++nf) {
                    const int p = nf >> 1, s2 = nf & 1;
                    MMA_F16(acc[mf][nf], al[mf], bf[p][s2], bf[p][s2 + 2]);
                }
        }

        if (c + 2 < NC) {
            int s2 = s + 2; if (s2 >= 3) s2 -= 3;
            prefetch(c + 2, s2);
        }
        if (++s == 3) s = 0;
    }

#pragma unroll
    for (int mf = 0; mf < 4; ++mf) {
#pragma unroll
        for (int nf = 0; nf < 4; ++nf) {
            const int r0 = wm * 64 + mf * 16 + (lane >> 2);
            const int cc = wn * 32 + nf * 8 + (lane & 3) * 2;
            float2 v0, v1;
            v0.x = acc[mf][nf][0] * scale; v0.y = acc[mf][nf][1] * scale;
            v1.x = acc[mf][nf][2] * scale; v1.y = acc[mf][nf][3] * scale;
            *(float2*)&Cb[(size_t)r0 * LSEQ + cc]       = v0;
            *(float2*)&Cb[(size_t)(r0 + 8) * LSEQ + cc] = v1;
        }
    }
}

// ---------------------------------------------------------------------------
// Kernel 3: row softmax over g_P -> fp16 attention g_af, for HALF the rows.
// Streaming (evict-first) loads of P; shuffle reductions.
// ---------------------------------------------------------------------------
__global__ __launch_bounds__(256) void softmax_kernel(int h)
{
    const size_t row = (size_t)h * (BATCH / 2) * LSEQ + blockIdx.x;
    const float* p = g_P + row * LSEQ;
    const int t = threadIdx.x;
    const int w = t >> 5;

    __shared__ float red[8];

    float v[8];
    {
        const float4 a = ldg_cs4((const float4*)p + t * 2);
        const float4 b = ldg_cs4((const float4*)p + t * 2 + 1);
        v[0] = a.x; v[1] = a.y; v[2] = a.z; v[3] = a.w;
        v[4] = b.x; v[5] = b.y; v[6] = b.z; v[7] = b.w;
    }
    float mx = v[0];
#pragma unroll
    for (int i = 1; i < 8; ++i) mx = fmaxf(mx, v[i]);
#pragma unroll
    for (int o = 16; o > 0; o >>= 1)
        mx = fmaxf(mx, __shfl_xor_sync(0xffffffffu, mx, o));
    if ((t & 31) == 0) red[w] = mx;
    __syncthreads();
    float m = red[0];
#pragma unroll
    for (int i = 1; i < 8; ++i) m = fmaxf(m, red[i]);
    __syncthreads();

    float sum = 0.0f;
#pragma unroll
    for (int i = 0; i < 8; ++i) {
        v[i] = __expf(v[i] - m);
        sum += v[i];
    }
#pragma unroll
    for (int o = 16; o > 0; o >>= 1)
        sum += __shfl_xor_sync(0xffffffffu, sum, o);
    if ((t & 31) == 0) red[w] = sum;
    __syncthreads();
    float tot = red[0];
#pragma unroll
    for (int i = 1; i < 8; ++i) tot += red[i];
    const float inv = 1.0f / tot;

    __half hh[8];
#pragma unroll
    for (int i = 0; i < 8; ++i) hh[i] = __float2half(v[i] * inv);
    *(uint4*)(g_af + row * LSEQ + t * 8) = *(const uint4*)hh;
}

// ---------------------------------------------------------------------------
// Kernel 4: AV single-product fp16 HMMA GEMM for HALF the batches.
// Tile 128x128, K-chunk 64, 3-stage cp.async. Grid (4, 16, 4) = 256 CTAs.
// ---------------------------------------------------------------------------
__global__ __launch_bounds__(256, 2) void av_kernel(float* __restrict__ Cout, int h)
{
    extern __shared__ __align__(128) char dsm[];

    constexpr int K       = LSEQ;
    constexpr int NC      = K / 64;        // 32
    constexpr int TILE_B  = 128 * 128;     // 16 KB
    constexpr int STAGE_B = 2 * TILE_B;    // 32 KB

    const int b  = h * (BATCH / 2) + blockIdx.z;
    const int n0 = blockIdx.x * 128;
    const int m0 = blockIdx.y * 128;
    const int t    = threadIdx.x;
    const int lane = t & 31;
    const int wid  = t >> 5;
    const int wm   = wid & 1;
    const int wn   = wid >> 1;

    const __half* pA = g_af  + ((size_t)b * LSEQ + m0) * LSEQ;
    const __half* pB = g_vtf + ((size_t)b * DDIM + n0) * LSEQ;
    float* Cb = Cout + ((size_t)b * LSEQ + m0) * DDIM + n0;

    const uint32_t sb = smem_u32(dsm);

    auto prefetch = [&](int c, int s) {
        const int k0 = c * 64;
        const uint32_t st = sb + s * STAGE_B;
        const __half* gs[2] = { pA + k0, pB + k0 };
#pragma unroll
        for (int tt = 0; tt < 2; ++tt) {
            const uint32_t tb = st + tt * TILE_B;
#pragma unroll
            for (int i = 0; i < 4; ++i) {
                const int li  = t + i * 256;
                const int row = li >> 3;
                const int seg = li & 7;
                CP_ASYNC16(tb + swz128(row, seg), gs[tt] + (size_t)row * LSEQ + seg * 8);
            }
        }
        CP_COMMIT();
    };

    float acc[4][4][4];
#pragma unroll
    for (int mf = 0; mf < 4; ++mf)
#pragma unroll
        for (int nf = 0; nf < 4; ++nf)
#pragma unroll
            for (int i = 0; i < 4; ++i) acc[mf][nf][i] = 0.0f;

    const int lr   = lane & 15;
    const int lseg = lane >> 4;

    prefetch(0, 0);
    prefetch(1, 1);

    int s = 0;
    for (int c = 0; c < NC; ++c) {
        if (c + 1 < NC) { CP_WAITN(1); } else { CP_WAITN(0); }
        __syncthreads();

        const uint32_t sA = sb + s * STAGE_B;
        const uint32_t sB = sA + TILE_B;

#pragma unroll
        for (int ks = 0; ks < 4; ++ks) {
            const int segk = ks * 2 + lseg;
            uint32_t a[4][4], bb[2][4];
#pragma unroll
            for (int mf = 0; mf < 4; ++mf)
                ldsm4(a[mf], sA + swz128(wm * 64 + mf * 16 + lr, segk));
#pragma unroll
            for (int p = 0; p < 2; ++p)
                ldsm4(bb[p], sB + swz128(wn * 32 + p * 16 + lr, segk));
#pragma unroll
            for (int mf = 0; mf < 4; ++mf)
#pragma unroll
                for (int nf = 0; nf < 4; ++nf) {
                    const int p = nf >> 1, s2 = nf & 1;
                    MMA_F16(acc[mf][nf], a[mf], bb[p][s2], bb[p][s2 + 2]);
                }
        }

        if (c + 2 < NC) {
            int s2 = s + 2; if (s2 >= 3) s2 -= 3;
            prefetch(c + 2, s2);
        }
        if (++s == 3) s = 0;
    }

#pragma unroll
    for (int mf = 0; mf < 4; ++mf) {
#pragma unroll
        for (int nf = 0; nf < 4; ++nf) {
            const int r0 = wm * 64 + mf * 16 + (lane >> 2);
            const int cc = wn * 32 + nf * 8 + (lane & 3) * 2;
            float2 v0, v1;
            v0.x = acc[mf][nf][0]; v0.y = acc[mf][nf][1];
            v1.x = acc[mf][nf][2]; v1.y = acc[mf][nf][3];
            *(float2*)&Cb[(size_t)r0 * DDIM + cc]       = v0;
            *(float2*)&Cb[(size_t)(r0 + 8) * DDIM + cc] = v1;
        }
    }
}

// ---------------------------------------------------------------------------
// Launch. split_qk -> [QK || split_v(s1)] -> sm_h0 -> [AV_h0 || sm_h1(s1)]
// -> AV_h1. Streams/events created per call and leaked (no device memory).
// ---------------------------------------------------------------------------
extern "C" void kernel_launch(void* const* d_in, const int* in_sizes, int n_in,
                              void* d_out, int out_size)
{
    const float* x  = (const float*)d_in[0];
    const float* qw = (const float*)d_in[1];
    const float* kw = (const float*)d_in[2];
    const float* vw = (const float*)d_in[3];
    float* out = (float*)d_out;

    constexpr int SMEM_QK = 73728;   // 3 stages x 24 KB
    constexpr int SMEM_AV = 98304;   // 3 stages x 32 KB
    cudaFuncSetAttribute(qk_kernel, cudaFuncAttributeMaxDynamicSharedMemorySize, SMEM_QK);
    cudaFuncSetAttribute(av_kernel, cudaFuncAttributeMaxDynamicSharedMemorySize, SMEM_AV);

    cudaStream_t s1;
    cudaStreamCreateWithFlags(&s1, cudaStreamNonBlocking);
    cudaEvent_t eSplit, eV, e0, e1;
    cudaEventCreateWithFlags(&eSplit, cudaEventDisableTiming);
    cudaEventCreateWithFlags(&eV, cudaEventDisableTiming);
    cudaEventCreateWithFlags(&e0, cudaEventDisableTiming);
    cudaEventCreateWithFlags(&e1, cudaEventDisableTiming);

    // q/k projection on main stream
    split_qk_kernel<<<dim3(LSEQ / 2, BATCH), 256>>>(x, qw, kw);
    cudaEventRecord(eSplit, 0);

    // v projection + transpose on side stream, overlapped with QK
    cudaStreamWaitEvent(s1, eSplit, 0);   // just ordering after input-ready; cheap
    split_v_kernel<<<dim3(LSEQ / 64, DDIM / 64, BATCH), 256, 0, s1>>>(x, vw);
    cudaEventRecord(eV, s1);

    qk_kernel<<<dim3(LSEQ / 128, LSEQ / 128, BATCH), 256, SMEM_QK>>>();

    // softmax half 0 on capture stream; half 1 forked to s1
    softmax_kernel<<<(BATCH / 2) * LSEQ, 256>>>(0);
    cudaEventRecord(e0, 0);
    cudaStreamWaitEvent(s1, e0, 0);
    softmax_kernel<<<(BATCH / 2) * LSEQ, 256, 0, s1>>>(1);
    cudaEventRecord(e1, s1);

    // AV half 0 overlaps sm half 1 (needs v^T ready)
    cudaStreamWaitEvent(0, eV, 0);
    av_kernel<<<dim3(DDIM / 128, LSEQ / 128, BATCH / 2), 256, SMEM_AV>>>(out, 0);
    cudaStreamWaitEvent(0, e1, 0);
    av_kernel<<<dim3(DDIM / 128, LSEQ / 128, BATCH / 2), 256, SMEM_AV>>>(out, 1);
}